// round 2
// baseline (speedup 1.0000x reference)
#include <cuda_runtime.h>
#include <cstdint>

// ---------------------------------------------------------------------------
// VectorQuantizerEMA on GB300 (sm_103a)
// B=64, D=128, T=2048, K=1024, N=B*T=131072
//
// Output layout (f32, concatenated in reference return order):
//   [0, 16777216)            out[b,d,t]  (straight-through quantized)
//   [16777216]               loss_commit
//   [16777217]               loss_vq
//   [16777218, 16908290)     idx (as float)
//   [16908290, 17039362)     new_embeddings [K, D]
//
// Argmin replicates the reference's fp32 rounding structure:
//   dist = fl32( fl32(|x|^2 + |e|^2) - 2*(x.e) ), ties -> lowest index.
// ---------------------------------------------------------------------------

#define B_   64
#define D_   128
#define T_   2048
#define K_   1024
#define N_   (B_ * T_)          // 131072
#define DT_  (D_ * T_)          // 262144
#define KD_  (K_ * D_)          // 131072

#define OUT_ELEMS   16777216
#define LOSS_OFF    16777216
#define IDX_OFF     16777218
#define EMB_OFF     16908290

#define D1F   ((float)(1.0 - 0.99))          // 1 - DECAY (== 1 - DECAY**COUNTER)
#define EPSF  1e-5f
#define KEPSF ((float)(1024 * 1e-5))

// -------- device-global scratch (no allocation allowed) --------
__device__ float  g_Et[D_ * K_];      // E transposed [D][K]
__device__ float  g_enorm[K_];        // fl32( exact |e_k|^2 )
__device__ float  g_dw[K_ * D_];      // scatter sums
__device__ float  g_counts[K_];
__device__ float  g_cs[K_];
__device__ double g_loss;

// -------- packed f32x2 helpers (Blackwell PTX) --------
#define FMA_X2(d, a, b) \
    asm("fma.rn.f32x2 %0, %1, %2, %0;" : "+l"(d) : "l"(a), "l"(b))
#define PACK_DUP(d, f) \
    asm("mov.b64 %0, {%1, %1};" : "=l"(d) : "f"(f))
#define UNPACK_X2(lo, hi, v) \
    asm("mov.b64 {%0, %1}, %2;" : "=f"(lo), "=f"(hi) : "l"(v))

// ---------------------------------------------------------------------------
// K0: build E^T and |e|^2 (fp64-exact, rounded to fp32). 1024 blocks x 128
// ---------------------------------------------------------------------------
__global__ void vq_prep(const float* __restrict__ E) {
    int k = blockIdx.x;
    int d = threadIdx.x;
    float v = E[k * D_ + d];
    g_Et[d * K_ + k] = v;
    double s = (double)v * (double)v;
    #pragma unroll
    for (int o = 16; o > 0; o >>= 1) s += __shfl_xor_sync(0xffffffffu, s, o);
    __shared__ double ws[4];
    if ((d & 31) == 0) ws[d >> 5] = s;
    __syncthreads();
    if (d == 0) g_enorm[k] = (float)((ws[0] + ws[1]) + (ws[2] + ws[3]));
}

// ---------------------------------------------------------------------------
// K1: fused distance GEMM + argmin + quantized-output + dw/counts/loss
// grid = (T/128, B) = (16, 64), 256 threads
// Tile: 128 tokens x 128 codes, loop 8 code-tiles; D chunked by 16.
// Thread (ty,tx) owns 8 tokens x 8 codes; codes packed in f32x2 pairs.
// ---------------------------------------------------------------------------
__global__ __launch_bounds__(256) void vq_main(
    const float* __restrict__ x,
    const float* __restrict__ E,
    float* __restrict__ out_q,     // d_out + 0
    float* __restrict__ out_idx)   // d_out + IDX_OFF
{
    const int b  = blockIdx.y;
    const int t0 = blockIdx.x * 128;
    const int tid = threadIdx.x;
    const int tx = tid & 15;       // code group
    const int ty = tid >> 4;       // token group

    extern __shared__ float sm[];
    float* xs      = sm;                      // [128 d][128 t]  16384
    float* es      = xs + 16384;              // [16 dd][128 k]   2048
    float* enorm_s = es + 2048;               // [1024]           1024
    float* red_v   = enorm_s + 1024;          // [128][16]        2048
    int*   red_i   = (int*)(red_v + 2048);    // [128][16]        2048
    int*   idx_s   = red_i + 2048;            // [128]             128
    float* As      = (float*)(idx_s + 128);   // [128] |x_t|^2     128

    // ---- stage full x tile (coalesced along t) ----
    const float* xb = x + (size_t)b * DT_ + t0;
    #pragma unroll
    for (int r = 0; r < 64; r++) {
        int e = tid + r * 256;
        int d = e >> 7, t = e & 127;
        xs[e] = xb[d * T_ + t];
    }
    for (int i = tid; i < K_; i += 256) enorm_s[i] = g_enorm[i];
    __syncthreads();

    // ---- per-token |x|^2 (fp64-exact -> fp32) ----
    if (tid < 128) {
        double a = 0.0;
        #pragma unroll 8
        for (int d = 0; d < 128; d++) {
            float xv = xs[d * 128 + tid];
            a += (double)xv * (double)xv;
        }
        As[tid] = (float)a;
    }
    __syncthreads();

    float a8[8];
    #pragma unroll
    for (int i = 0; i < 8; i++) a8[i] = As[ty * 8 + i];

    float rmin[8];
    int   ridx[8];
    #pragma unroll
    for (int i = 0; i < 8; i++) { rmin[i] = 3.4e38f; ridx[i] = 0; }

    for (int ct = 0; ct < 8; ct++) {
        unsigned long long acc[8][4];
        #pragma unroll
        for (int i = 0; i < 8; i++)
            #pragma unroll
            for (int j = 0; j < 4; j++) acc[i][j] = 0ULL;

        for (int dc = 0; dc < 8; dc++) {
            __syncthreads();
            #pragma unroll
            for (int r = 0; r < 8; r++) {
                int e = tid + r * 256;
                int dd = e >> 7, kk = e & 127;
                es[e] = g_Et[(dc * 16 + dd) * K_ + ct * 128 + kk];
            }
            __syncthreads();

            #pragma unroll
            for (int dd = 0; dd < 16; dd++) {
                const float4* ar =
                    (const float4*)&xs[(dc * 16 + dd) * 128 + ty * 8];
                float4 a0 = ar[0];
                float4 a1 = ar[1];
                const unsigned long long* br =
                    (const unsigned long long*)&es[dd * 128 + tx * 8];
                unsigned long long b0 = br[0], b1 = br[1],
                                   b2 = br[2], b3 = br[3];
                float av[8] = {a0.x, a0.y, a0.z, a0.w,
                               a1.x, a1.y, a1.z, a1.w};
                #pragma unroll
                for (int i = 0; i < 8; i++) {
                    unsigned long long ad;
                    PACK_DUP(ad, av[i]);
                    FMA_X2(acc[i][0], ad, b0);
                    FMA_X2(acc[i][1], ad, b1);
                    FMA_X2(acc[i][2], ad, b2);
                    FMA_X2(acc[i][3], ad, b3);
                }
            }
        }

        // ---- fold into running argmin, replicating reference rounding:
        //      dist = fl32( fl32(A + B_k) - 2*s_k ), strict < keeps lowest idx
        #pragma unroll
        for (int i = 0; i < 8; i++) {
            #pragma unroll
            for (int jp = 0; jp < 4; jp++) {
                float s0, s1;
                UNPACK_X2(s0, s1, acc[i][jp]);
                int col = ct * 128 + tx * 8 + jp * 2;
                float ab0 = __fadd_rn(a8[i], enorm_s[col]);
                float ab1 = __fadd_rn(a8[i], enorm_s[col + 1]);
                float v0 = __fadd_rn(ab0, -2.0f * s0);
                float v1 = __fadd_rn(ab1, -2.0f * s1);
                if (v0 < rmin[i]) { rmin[i] = v0; ridx[i] = col; }
                if (v1 < rmin[i]) { rmin[i] = v1; ridx[i] = col + 1; }
            }
        }
    }

    // ---- cross-thread argmin reduction (lowest index on exact tie) ----
    __syncthreads();
    #pragma unroll
    for (int i = 0; i < 8; i++) {
        int t = ty * 8 + i;
        red_v[t * 16 + tx] = rmin[i];
        red_i[t * 16 + tx] = ridx[i];
    }
    __syncthreads();
    if (tid < 128) {
        float best = red_v[tid * 16];
        int   bi   = red_i[tid * 16];
        #pragma unroll
        for (int s = 1; s < 16; s++) {
            float v = red_v[tid * 16 + s];
            int  ii = red_i[tid * 16 + s];
            if (v < best || (v == best && ii < bi)) { best = v; bi = ii; }
        }
        idx_s[tid] = bi;
        out_idx[b * T_ + t0 + tid] = (float)bi;
        atomicAdd(&g_counts[bi], 1.0f);
    }
    __syncthreads();

    // ---- epilogue: straight-through output, dw scatter, loss ----
    const int t   = tid & 127;           // fixed per thread -> coalesced stores
    const int d0  = tid >> 7;
    const int myk = idx_s[t];
    const float* erow = E + myk * D_;
    float* ob = out_q + (size_t)b * DT_ + t0 + t;
    float* dwr = &g_dw[myk * D_];
    float lsum = 0.0f;
    #pragma unroll 4
    for (int r = 0; r < 64; r++) {
        int d = d0 + 2 * r;
        float xv = xs[d * 128 + t];
        float ev = erow[d];
        // replicate ref: q_st = xt + (quantized - xt), elementwise fp32
        ob[(size_t)d * T_] = __fadd_rn(xv, __fsub_rn(ev, xv));
        atomicAdd(&dwr[d], xv);
        float df = xv - ev;
        lsum += df * df;
    }
    #pragma unroll
    for (int o = 16; o > 0; o >>= 1)
        lsum += __shfl_xor_sync(0xffffffffu, lsum, o);
    if ((tid & 31) == 0) red_v[tid >> 5] = lsum;
    __syncthreads();
    if (tid == 0) {
        float s = 0.0f;
        #pragma unroll
        for (int w = 0; w < 8; w++) s += red_v[w];
        atomicAdd(&g_loss, (double)s);
    }
}

// ---------------------------------------------------------------------------
// K3a: cluster-size EMA + Laplace smoothing + losses.  1 block, 1024 threads
// ---------------------------------------------------------------------------
__global__ void vq_stats(const float* __restrict__ ema_c,
                         float* __restrict__ out_loss) {
    int k = threadIdx.x;
    float c   = g_counts[k];
    float ema = ema_c[k];
    float hid = ema - (ema - c) * D1F;
    float avg = hid / D1F;
    __shared__ float sred[1024];
    sred[k] = avg;
    __syncthreads();
    for (int o = 512; o > 0; o >>= 1) {
        if (k < o) sred[k] += sred[k + o];
        __syncthreads();
    }
    float n = sred[0];
    g_cs[k] = (avg + EPSF) / (n + KEPSF) * n;
    if (k == 0) {
        float mse = (float)(g_loss / 16777216.0);
        out_loss[0] = 0.25f * mse;   // loss_commit
        out_loss[1] = mse;           // loss_vq
    }
}

// ---------------------------------------------------------------------------
// K3b: new_embeddings = avg_dw / cs.  512 blocks x 256
// ---------------------------------------------------------------------------
__global__ void vq_emb(const float* __restrict__ ema_dw,
                       float* __restrict__ out_emb) {
    int e = blockIdx.x * 256 + threadIdx.x;   // < 131072
    int k = e >> 7;
    float dwv = g_dw[e];
    float ema = ema_dw[e];
    float hid = ema - (ema - dwv) * D1F;
    float avg = hid / D1F;
    out_emb[e] = avg / g_cs[k];
}

// ---------------------------------------------------------------------------
extern "C" void kernel_launch(void* const* d_in, const int* in_sizes, int n_in,
                              void* d_out, int out_size) {
    const float* x      = (const float*)d_in[0];
    const float* E      = (const float*)d_in[1];
    const float* ema_dw = (const float*)d_in[2];
    const float* ema_c  = (const float*)d_in[3];
    float* out = (float*)d_out;

    void *p_dw = nullptr, *p_cnt = nullptr, *p_loss = nullptr;
    cudaGetSymbolAddress(&p_dw, g_dw);
    cudaGetSymbolAddress(&p_cnt, g_counts);
    cudaGetSymbolAddress(&p_loss, g_loss);
    cudaMemsetAsync(p_dw, 0, K_ * D_ * sizeof(float));
    cudaMemsetAsync(p_cnt, 0, K_ * sizeof(float));
    cudaMemsetAsync(p_loss, 0, sizeof(double));

    vq_prep<<<K_, 128>>>(E);

    const int smem = 95232;
    cudaFuncSetAttribute(vq_main, cudaFuncAttributeMaxDynamicSharedMemorySize,
                         smem);
    dim3 grid(T_ / 128, B_);
    vq_main<<<grid, 256, smem>>>(x, E, out, out + IDX_OFF);

    vq_stats<<<1, 1024>>>(ema_c, out + LOSS_OFF);
    vq_emb<<<KD_ / 256, 256>>>(ema_dw, out + EMB_OFF);
}